// round 7
// baseline (speedup 1.0000x reference)
#include <cuda_runtime.h>
#include <math.h>
#include <stdint.h>

#define NN   50000
#define EE   800000
#define GG   256
#define IND  32
#define HID  108
#define H2   54
#define H4   27
#define NCLS 10
#define NB   196   // scan blocks = ceil(NN/256)
#define GNB  64    // nodes per block for gsum

// ---- mma GEMM tiling (512 threads, 128-node tiles) ----
#define SXS   132  // sX stride (floats): conflict-free scalar A loads
#define SWS2  120  // sW stride (float2): LDS.64 B loads (2-way, acceptable)
#define KPAD  112  // padded K per pass (14 chunks of 8)
#define MTPB  512

// ---- embed (FFMA2 path) ----
#define NT    64
#define TPB   224
#define NCG   28
#define WSTR  112
#define NSTR  68
#define FMA2(acc, x, w) asm("fma.rn.f32x2 %0, %1, %2, %0;" : "+l"(acc) : "l"(x), "l"(w))
#define PACKDUP(out, f) asm("mov.b64 %0, {%1, %1};" : "=l"(out) : "r"(__float_as_uint(f)))
__device__ __forceinline__ float lo32(unsigned long long u) { return __uint_as_float((unsigned)u); }
__device__ __forceinline__ float hi32(unsigned long long u) { return __uint_as_float((unsigned)(u >> 32)); }

// ---------------- scratch ----------------
__device__ float d_hA[NN * HID];
__device__ float d_hB[NN * HID];
__device__ float d_hp[NN * HID];
__device__ float d_agg[NN * HID];
__device__ int   d_cnt[NN];
__device__ int   d_bsum[256];
__device__ int   d_boff[256];
__device__ int   d_rowptr[NN + 1];
__device__ int   d_cursor[NN];
__device__ int   d_colsrc[EE];
__device__ float d_gsum[GG * HID];
__device__ float d_gcnt[GG];
__device__ float2 d_Wpool2[4 * HID * HID];       // pre-split pool weights (hi, lo)
__device__ float2 d_Wapp2[4 * 2 * HID * HID];    // pre-split apply weights (hi, lo)

// ---------------- tf32 helpers ----------------
__device__ __forceinline__ void cvt_split(float x, uint32_t& hi, uint32_t& lo) {
    uint32_t h;
    asm("cvt.rna.tf32.f32 %0, %1;" : "=r"(h) : "f"(x));
    float r = x - __uint_as_float(h);
    uint32_t l;
    asm("cvt.rna.tf32.f32 %0, %1;" : "=r"(l) : "f"(r));
    hi = h; lo = l;
}

__device__ __forceinline__ void mma8(float acc[4], const uint32_t a[4], uint32_t b0, uint32_t b1) {
    asm volatile("mma.sync.aligned.m16n8k8.row.col.f32.tf32.tf32.f32 "
                 "{%0,%1,%2,%3}, {%4,%5,%6,%7}, {%8,%9}, {%0,%1,%2,%3};"
                 : "+f"(acc[0]), "+f"(acc[1]), "+f"(acc[2]), "+f"(acc[3])
                 : "r"(a[0]), "r"(a[1]), "r"(a[2]), "r"(a[3]), "r"(b0), "r"(b1));
}

// ---------------- weight pre-split ----------------
__global__ void k_wsplit(const float* __restrict__ W, float2* __restrict__ out, int n) {
    int i = blockIdx.x * blockDim.x + threadIdx.x;
    if (i >= n) return;
    float w = W[i];
    uint32_t h, l;
    cvt_split(w, h, l);
    out[i] = make_float2(__uint_as_float(h), __uint_as_float(l));
}

// ---------------- utility ----------------
__global__ void k_zero(float* __restrict__ p, int n) {
    int i = blockIdx.x * blockDim.x + threadIdx.x;
    if (i < n) p[i] = 0.f;
}
__global__ void k_zero_int(int* __restrict__ p, int n) {
    int i = blockIdx.x * blockDim.x + threadIdx.x;
    if (i < n) p[i] = 0;
}

// ---------------- CSR build ----------------
__global__ void k_hist(const int* __restrict__ dst, int* __restrict__ cnt) {
    int e = blockIdx.x * blockDim.x + threadIdx.x;
    if (e < EE) atomicAdd(&cnt[dst[e]], 1);
}

__global__ void k_bsum(const int* __restrict__ cnt, int* __restrict__ bsum) {
    __shared__ int s[256];
    int i = blockIdx.x * 256 + threadIdx.x;
    s[threadIdx.x] = (i < NN) ? cnt[i] : 0;
    __syncthreads();
    for (int o = 128; o > 0; o >>= 1) {
        if (threadIdx.x < o) s[threadIdx.x] += s[threadIdx.x + o];
        __syncthreads();
    }
    if (threadIdx.x == 0) bsum[blockIdx.x] = s[0];
}

__global__ void k_scan_tops(const int* __restrict__ bsum, int* __restrict__ boff) {
    __shared__ int s[256];
    int t = threadIdx.x;
    int v = (t < NB) ? bsum[t] : 0;
    s[t] = v;
    __syncthreads();
    for (int o = 1; o < 256; o <<= 1) {
        int tv = (t >= o) ? s[t - o] : 0;
        __syncthreads();
        s[t] += tv;
        __syncthreads();
    }
    if (t < NB) boff[t] = s[t] - v;
}

__global__ void k_scan_block(const int* __restrict__ cnt, const int* __restrict__ boff,
                             int* __restrict__ rowptr, int* __restrict__ cursor) {
    __shared__ int s[256];
    int t = threadIdx.x;
    int i = blockIdx.x * 256 + t;
    int v = (i < NN) ? cnt[i] : 0;
    s[t] = v;
    __syncthreads();
    for (int o = 1; o < 256; o <<= 1) {
        int tv = (t >= o) ? s[t - o] : 0;
        __syncthreads();
        s[t] += tv;
        __syncthreads();
    }
    int excl = s[t] - v + boff[blockIdx.x];
    if (i < NN) { rowptr[i] = excl; cursor[i] = excl; }
    if (i == NN - 1) rowptr[NN] = excl + v;
}

__global__ void k_scatter(const int* __restrict__ src, const int* __restrict__ dst,
                          int* __restrict__ cursor, int* __restrict__ colsrc) {
    int e = blockIdx.x * blockDim.x + threadIdx.x;
    if (e < EE) {
        int pos = atomicAdd(&cursor[dst[e]], 1);
        colsrc[pos] = src[e];
    }
}

// ============ fill helpers for mma kernels (512 threads) ============
// sWp[k][c] float2 (hi,lo), stride SWS2; real data rows 0..107, cols 0..107
__device__ __forceinline__ void mfill_W2(float2* sWp, const float2* __restrict__ gW, int t) {
    const float4* g4 = (const float4*)gW;   // 2 float2 per float4
    for (int i = t; i < 108 * 54; i += MTPB) {
        int k = i / 54, q = i % 54;
        *(float4*)&sWp[k * SWS2 + 2 * q] = g4[i];
    }
    // pad cols 108..119 rows 0..107, and rows 108..111 fully
    for (int i = t; i < 108 * 6; i += MTPB) {
        int k = i / 6, j = i % 6;
        *(float4*)&sWp[k * SWS2 + 108 + 2 * j] = make_float4(0.f, 0.f, 0.f, 0.f);
    }
    for (int i = t; i < 4 * 60; i += MTPB) {
        int k = 108 + i / 60, j = i % 60;
        *(float4*)&sWp[k * SWS2 + 2 * j] = make_float4(0.f, 0.f, 0.f, 0.f);
    }
}

// sX[n][k] fp32, stride SXS, 128 nodes, cols 0..131 (real 0..107)
__device__ __forceinline__ void mfill_X(float* sX, const float* __restrict__ M, int nb, int t) {
    const float4* M4 = (const float4*)M;
    for (int i = t; i < 128 * 27; i += MTPB) {
        int n = i / 27, q = i % 27;
        int node = nb + n;
        float4 v = make_float4(0.f, 0.f, 0.f, 0.f);
        if (node < NN) v = M4[(long)node * 27 + q];
        *(float4*)&sX[n * SXS + 4 * q] = v;
    }
    for (int i = t; i < 128 * 6; i += MTPB) {
        int n = i / 6, j = i % 6;
        *(float4*)&sX[n * SXS + 108 + 4 * j] = make_float4(0.f, 0.f, 0.f, 0.f);
    }
}

// warp tile: 16 nodes x 56 cols; A converted on the fly, B pre-split in SMEM
__device__ __forceinline__ void mma_pass(const float* sX, const float2* sWp,
                                         int n16, int cbase0, int gid, int tig,
                                         float acc[7][4]) {
#pragma unroll 2
    for (int kc = 0; kc < KPAD; kc += 8) {
        uint32_t ah[4], al[4];
        cvt_split(sX[(n16 + gid) * SXS + kc + tig],         ah[0], al[0]);
        cvt_split(sX[(n16 + gid + 8) * SXS + kc + tig],     ah[1], al[1]);
        cvt_split(sX[(n16 + gid) * SXS + kc + tig + 4],     ah[2], al[2]);
        cvt_split(sX[(n16 + gid + 8) * SXS + kc + tig + 4], ah[3], al[3]);
#pragma unroll
        for (int j = 0; j < 7; j++) {
            int c = cbase0 + 8 * j + gid;
            float2 w0 = sWp[(kc + tig) * SWS2 + c];      // (hi, lo) at k=tig
            float2 w1 = sWp[(kc + tig + 4) * SWS2 + c];  // (hi, lo) at k=tig+4
            uint32_t bh0 = __float_as_uint(w0.x), bl0 = __float_as_uint(w0.y);
            uint32_t bh1 = __float_as_uint(w1.x), bl1 = __float_as_uint(w1.y);
            mma8(acc[j], ah, bl0, bl1);   // hi*lo
            mma8(acc[j], al, bh0, bh1);   // lo*hi
            mma8(acc[j], ah, bh0, bh1);   // hi*hi
        }
    }
}

// ---------------- pool: hp = relu(h @ W + b), tf32 mma ----------------
__global__ __launch_bounds__(MTPB, 1) void k_pool5(const float* __restrict__ h,
                                                   const float2* __restrict__ gW,
                                                   const float* __restrict__ b,
                                                   float* __restrict__ out) {
    extern __shared__ float sm[];
    float* sX = sm;                               // 128*SXS floats
    float2* sWp = (float2*)(sm + 128 * SXS);      // KPAD*SWS2 float2
    __shared__ float sb[112];
    int t = threadIdx.x;
    int warp = t >> 5, lane = t & 31;
    int gid = lane >> 2, tig = lane & 3;
    int n16 = (warp & 7) * 16;
    int cbase0 = (warp >> 3) * 56;
    int nb = blockIdx.x * 128;

    mfill_W2(sWp, gW, t);
    mfill_X(sX, h, nb, t);
    if (t < 112) sb[t] = (t < 108) ? b[t] : 0.f;
    __syncthreads();

    float acc[7][4];
#pragma unroll
    for (int j = 0; j < 7; j++)
#pragma unroll
        for (int p = 0; p < 4; p++) acc[j][p] = 0.f;

    mma_pass(sX, sWp, n16, cbase0, gid, tig, acc);

    int node0 = nb + n16 + gid;
    int node1 = node0 + 8;
#pragma unroll
    for (int j = 0; j < 7; j++) {
        int c = cbase0 + 8 * j + 2 * tig;
        if (c < 108) {
            float bx = sb[c], by = sb[c + 1];
            if (node0 < NN) {
                float2 v = make_float2(fmaxf(acc[j][0] + bx, 0.f), fmaxf(acc[j][1] + by, 0.f));
                *(float2*)&out[(long)node0 * HID + c] = v;
            }
            if (node1 < NN) {
                float2 v = make_float2(fmaxf(acc[j][2] + bx, 0.f), fmaxf(acc[j][3] + by, 0.f));
                *(float2*)&out[(long)node1 * HID + c] = v;
            }
        }
    }
}

// ---- apply: h' = h + relu(l2norm(concat(h, agg) @ W + b)), 2-pass ----
__global__ __launch_bounds__(MTPB, 1) void k_apply5(const float* __restrict__ h,
                                                    const float* __restrict__ agg,
                                                    const float2* __restrict__ gW,
                                                    const float* __restrict__ b,
                                                    float* __restrict__ hout) {
    extern __shared__ float sm[];
    float* sX = sm;
    float2* sWp = (float2*)(sm + 128 * SXS);
    __shared__ float sb[112];
    __shared__ float sqsm[2][128];
    __shared__ float snorm[128];
    int t = threadIdx.x;
    int warp = t >> 5, lane = t & 31;
    int gid = lane >> 2, tig = lane & 3;
    int n16 = (warp & 7) * 16;
    int ch = warp >> 3;
    int cbase0 = ch * 56;
    int nb = blockIdx.x * 128;

    if (t < 112) sb[t] = (t < 108) ? b[t] : 0.f;

    float acc[7][4];
#pragma unroll
    for (int j = 0; j < 7; j++)
#pragma unroll
        for (int p = 0; p < 4; p++) acc[j][p] = 0.f;

    // pass 0: h x W[0:108]
    mfill_W2(sWp, gW, t);
    mfill_X(sX, h, nb, t);
    __syncthreads();
    mma_pass(sX, sWp, n16, cbase0, gid, tig, acc);
    __syncthreads();
    // pass 1: agg x W[108:216]
    mfill_W2(sWp, gW + HID * HID, t);
    mfill_X(sX, agg, nb, t);
    __syncthreads();
    mma_pass(sX, sWp, n16, cbase0, gid, tig, acc);

    // bias + partial sum of squares per row
    float sq0 = 0.f, sq1 = 0.f;
#pragma unroll
    for (int j = 0; j < 7; j++) {
        int c = cbase0 + 8 * j + 2 * tig;
        if (c < 108) {
            float bx = sb[c], by = sb[c + 1];
            acc[j][0] += bx; acc[j][1] += by;
            acc[j][2] += bx; acc[j][3] += by;
            sq0 += acc[j][0] * acc[j][0] + acc[j][1] * acc[j][1];
            sq1 += acc[j][2] * acc[j][2] + acc[j][3] * acc[j][3];
        }
    }
    sq0 += __shfl_xor_sync(0xffffffffu, sq0, 1);
    sq0 += __shfl_xor_sync(0xffffffffu, sq0, 2);
    sq1 += __shfl_xor_sync(0xffffffffu, sq1, 1);
    sq1 += __shfl_xor_sync(0xffffffffu, sq1, 2);
    if (tig == 0) {
        sqsm[ch][n16 + gid] = sq0;
        sqsm[ch][n16 + gid + 8] = sq1;
    }
    __syncthreads();
    if (t < 128) {
        float s = sqsm[0][t] + sqsm[1][t];
        snorm[t] = 1.f / fmaxf(sqrtf(s), 1e-12f);
    }
    __syncthreads();

    int node0 = nb + n16 + gid;
    int node1 = node0 + 8;
    float nrm0 = snorm[n16 + gid], nrm1 = snorm[n16 + gid + 8];
#pragma unroll
    for (int j = 0; j < 7; j++) {
        int c = cbase0 + 8 * j + 2 * tig;
        if (c < 108) {
            if (node0 < NN) {
                float2 hv = *(const float2*)&h[(long)node0 * HID + c];
                float2 v = make_float2(hv.x + fmaxf(acc[j][0] * nrm0, 0.f),
                                       hv.y + fmaxf(acc[j][1] * nrm0, 0.f));
                *(float2*)&hout[(long)node0 * HID + c] = v;
            }
            if (node1 < NN) {
                float2 hv = *(const float2*)&h[(long)node1 * HID + c];
                float2 v = make_float2(hv.x + fmaxf(acc[j][2] * nrm1, 0.f),
                                       hv.y + fmaxf(acc[j][3] * nrm1, 0.f));
                *(float2*)&hout[(long)node1 * HID + c] = v;
            }
        }
    }
}

// ============ embed (FFMA2 path, K=32) ============
__device__ __forceinline__ void fill_xT(float* xT, const float* __restrict__ M,
                                        int nb, int kdim, int t) {
    const float4* M4 = (const float4*)M;
    int q4 = kdim >> 2;
    for (int i = t; i < NT * q4; i += TPB) {
        int n = i / q4, q = i % q4;
        int node = nb + n;
        float4 v = make_float4(0.f, 0.f, 0.f, 0.f);
        if (node < NN) v = M4[(long)node * q4 + q];
        int kb = 4 * q;
        xT[(kb + 0) * NSTR + n] = v.x;
        xT[(kb + 1) * NSTR + n] = v.y;
        xT[(kb + 2) * NSTR + n] = v.z;
        xT[(kb + 3) * NSTR + n] = v.w;
    }
}

__device__ __forceinline__ void fill_W(float* sW, const float* __restrict__ W,
                                       int kdim, int t) {
    for (int i = t; i < kdim * HID; i += TPB) {
        int k = i / HID, c = i % HID;
        sW[k * WSTR + c] = W[i];
    }
    for (int i = t; i < kdim * 4; i += TPB) {
        int k = i >> 2;
        sW[k * WSTR + HID + (i & 3)] = 0.f;
    }
}

__device__ __forceinline__ void accum(const float* sW, const float* xT, int kdim,
                                      int cg, int n0, unsigned long long acc[4][4]) {
#pragma unroll 4
    for (int k = 0; k < kdim; k++) {
        float4 w = *(const float4*)&sW[k * WSTR + 4 * cg];
        ulonglong2 Xa = *(const ulonglong2*)&xT[k * NSTR + n0];
        ulonglong2 Xb = *(const ulonglong2*)&xT[k * NSTR + n0 + 4];
        unsigned long long w0, w1, w2, w3;
        PACKDUP(w0, w.x); PACKDUP(w1, w.y); PACKDUP(w2, w.z); PACKDUP(w3, w.w);
        FMA2(acc[0][0], Xa.x, w0); FMA2(acc[0][1], Xa.y, w0);
        FMA2(acc[0][2], Xb.x, w0); FMA2(acc[0][3], Xb.y, w0);
        FMA2(acc[1][0], Xa.x, w1); FMA2(acc[1][1], Xa.y, w1);
        FMA2(acc[1][2], Xb.x, w1); FMA2(acc[1][3], Xb.y, w1);
        FMA2(acc[2][0], Xa.x, w2); FMA2(acc[2][1], Xa.y, w2);
        FMA2(acc[2][2], Xb.x, w2); FMA2(acc[2][3], Xb.y, w2);
        FMA2(acc[3][0], Xa.x, w3); FMA2(acc[3][1], Xa.y, w3);
        FMA2(acc[3][2], Xb.x, w3); FMA2(acc[3][3], Xb.y, w3);
    }
}

__global__ __launch_bounds__(TPB) void k_embed4(const float* __restrict__ x,
                                                const float* __restrict__ W,
                                                const float* __restrict__ b,
                                                float* __restrict__ out) {
    __shared__ float sW[IND * WSTR];
    __shared__ float xT[IND * NSTR];
    int t = threadIdx.x;
    int cg = t % NCG, ng = t / NCG;
    int n0 = 8 * ng;
    int nb = blockIdx.x * NT;
    fill_W(sW, W, IND, t);
    fill_xT(xT, x, nb, IND, t);
    __syncthreads();
    unsigned long long acc[4][4];
#pragma unroll
    for (int j = 0; j < 4; j++)
#pragma unroll
        for (int p = 0; p < 4; p++) acc[j][p] = 0ull;
    accum(sW, xT, IND, cg, n0, acc);
    if (cg < 27) {
        int c0 = 4 * cg;
        float4 bias = *(const float4*)&b[c0];
#pragma unroll
        for (int p = 0; p < 4; p++) {
            int na = nb + n0 + 2 * p, nc = na + 1;
            if (na < NN) {
                float4 v = make_float4(lo32(acc[0][p]) + bias.x, lo32(acc[1][p]) + bias.y,
                                       lo32(acc[2][p]) + bias.z, lo32(acc[3][p]) + bias.w);
                *(float4*)&out[(long)na * HID + c0] = v;
            }
            if (nc < NN) {
                float4 v = make_float4(hi32(acc[0][p]) + bias.x, hi32(acc[1][p]) + bias.y,
                                       hi32(acc[2][p]) + bias.z, hi32(acc[3][p]) + bias.w);
                *(float4*)&out[(long)nc * HID + c0] = v;
            }
        }
    }
}

// ---------------- aggregation via CSR ----------------
__global__ void k_agg3(const float* __restrict__ hp, const int* __restrict__ rowptr,
                       const int* __restrict__ colsrc, float* __restrict__ agg) {
    int w = (blockIdx.x * blockDim.x + threadIdx.x) >> 5;
    int lane = threadIdx.x & 31;
    if (w >= NN) return;
    int r0 = rowptr[w], r1 = rowptr[w + 1];
    float4 acc = make_float4(0.f, 0.f, 0.f, 0.f);
    const float4* hp4 = (const float4*)hp;
    for (int j0 = r0; j0 < r1; j0 += 32) {
        int myj = j0 + lane;
        int sreg = (myj < r1) ? colsrc[myj] : 0;
        int cnt = min(32, r1 - j0);
#pragma unroll 4
        for (int u = 0; u < cnt; u++) {
            int s = __shfl_sync(0xffffffffu, sreg, u);
            if (lane < 27) {
                float4 v = hp4[(long)s * 27 + lane];
                acc.x += v.x; acc.y += v.y; acc.z += v.z; acc.w += v.w;
            }
        }
    }
    float inv = 1.f / fmaxf((float)(r1 - r0), 1.f);
    if (lane < 27) {
        acc.x *= inv; acc.y *= inv; acc.z *= inv; acc.w *= inv;
        ((float4*)agg)[(long)w * 27 + lane] = acc;
    }
}

// ---------------- readout ----------------
__global__ void k_gsum2(const float* __restrict__ h, const int* __restrict__ gid,
                        float* __restrict__ gsum, float* __restrict__ gcnt) {
    int t = threadIdx.x;
    if (t >= HID) return;
    int n0 = blockIdx.x * GNB;
    int n1 = min(n0 + GNB, NN);
    int gprev = __ldg(&gid[n0]);
    float accv = 0.f, cntv = 0.f;
    for (int n = n0; n < n1; n++) {
        int g = __ldg(&gid[n]);
        if (g != gprev) {
            atomicAdd(&gsum[(long)gprev * HID + t], accv);
            if (t == 0) atomicAdd(&gcnt[gprev], cntv);
            accv = 0.f; cntv = 0.f; gprev = g;
        }
        accv += h[(long)n * HID + t];
        cntv += 1.f;
    }
    atomicAdd(&gsum[(long)gprev * HID + t], accv);
    if (t == 0) atomicAdd(&gcnt[gprev], cntv);
}

__global__ void k_mlp(const float* __restrict__ gsum, const float* __restrict__ gcnt,
                      const float* __restrict__ W1, const float* __restrict__ b1,
                      const float* __restrict__ W2, const float* __restrict__ b2,
                      const float* __restrict__ W3, const float* __restrict__ b3,
                      float* __restrict__ out) {
    __shared__ float hg[HID];
    __shared__ float y1[H2];
    __shared__ float y2[H4];
    int g = blockIdx.x, t = threadIdx.x;
    float ic = 1.f / fmaxf(gcnt[g], 1.f);
    if (t < HID) hg[t] = gsum[g * HID + t] * ic;
    __syncthreads();
    if (t < H2) {
        float a = b1[t];
#pragma unroll 4
        for (int k = 0; k < HID; k++) a += hg[k] * W1[k * H2 + t];
        y1[t] = fmaxf(a, 0.f);
    }
    __syncthreads();
    if (t < H4) {
        float a = b2[t];
#pragma unroll 6
        for (int k = 0; k < H2; k++) a += y1[k] * W2[k * H4 + t];
        y2[t] = fmaxf(a, 0.f);
    }
    __syncthreads();
    if (t < NCLS) {
        float a = b3[t];
#pragma unroll
        for (int k = 0; k < H4; k++) a += y2[k] * W3[k * NCLS + t];
        out[g * NCLS + t] = a;
    }
}

// ---------------- host launcher ----------------
extern "C" void kernel_launch(void* const* d_in, const int* in_sizes, int n_in,
                              void* d_out, int out_size) {
    const float* nodes_feat = (const float*)d_in[0];
    const int* src = (const int*)d_in[4];
    const int* dst = (const int*)d_in[5];
    const int* gid = (const int*)d_in[6];
    const float* W_emb = (const float*)d_in[7];
    const float* b_emb = (const float*)d_in[8];
    const float* W_pool = (const float*)d_in[9];
    const float* b_pool = (const float*)d_in[10];
    const float* W_app = (const float*)d_in[11];
    const float* b_app = (const float*)d_in[12];
    const float* W1 = (const float*)d_in[13];
    const float* b1 = (const float*)d_in[14];
    const float* W2 = (const float*)d_in[15];
    const float* b2 = (const float*)d_in[16];
    const float* W3 = (const float*)d_in[17];
    const float* b3 = (const float*)d_in[18];
    float* out = (float*)d_out;

    float *hA, *hB, *hp, *agg, *gsum, *gcnt;
    int *cnt, *bsum, *boff, *rowptr, *cursor, *colsrc;
    float2 *Wp2, *Wa2;
    cudaGetSymbolAddress((void**)&hA, d_hA);
    cudaGetSymbolAddress((void**)&hB, d_hB);
    cudaGetSymbolAddress((void**)&hp, d_hp);
    cudaGetSymbolAddress((void**)&agg, d_agg);
    cudaGetSymbolAddress((void**)&cnt, d_cnt);
    cudaGetSymbolAddress((void**)&bsum, d_bsum);
    cudaGetSymbolAddress((void**)&boff, d_boff);
    cudaGetSymbolAddress((void**)&rowptr, d_rowptr);
    cudaGetSymbolAddress((void**)&cursor, d_cursor);
    cudaGetSymbolAddress((void**)&colsrc, d_colsrc);
    cudaGetSymbolAddress((void**)&gsum, d_gsum);
    cudaGetSymbolAddress((void**)&gcnt, d_gcnt);
    cudaGetSymbolAddress((void**)&Wp2, d_Wpool2);
    cudaGetSymbolAddress((void**)&Wa2, d_Wapp2);

    const int mma_smem = (128 * SXS) * (int)sizeof(float) + (KPAD * SWS2) * (int)sizeof(float2);
    cudaFuncSetAttribute(k_pool5, cudaFuncAttributeMaxDynamicSharedMemorySize, mma_smem);
    cudaFuncSetAttribute(k_apply5, cudaFuncAttributeMaxDynamicSharedMemorySize, mma_smem);

    const int embed_blocks = (NN + NT - 1) / NT;
    const int mma_blocks = (NN + 127) / 128;

    // order arranged so ncu (-s 5 -c 1) captures k_pool5 (6th launch)
    k_embed4<<<embed_blocks, TPB>>>(nodes_feat, W_emb, b_emb, hA);                  // 1
    k_wsplit<<<(4 * HID * HID + 255) / 256, 256>>>(W_pool, Wp2, 4 * HID * HID);     // 2
    k_wsplit<<<(8 * HID * HID + 255) / 256, 256>>>(W_app, Wa2, 8 * HID * HID);      // 3
    k_zero_int<<<(NN + 255) / 256, 256>>>(cnt, NN);                                 // 4
    k_hist<<<(EE + 255) / 256, 256>>>(dst, cnt);                                    // 5
    k_pool5<<<mma_blocks, MTPB, mma_smem>>>(hA, Wp2, b_pool, hp);                   // 6 <- profiled
    k_bsum<<<NB, 256>>>(cnt, bsum);                                                 // 7
    k_scan_tops<<<1, 256>>>(bsum, boff);                                            // 8
    k_scan_block<<<NB, 256>>>(cnt, boff, rowptr, cursor);                           // 9
    k_scatter<<<(EE + 255) / 256, 256>>>(src, dst, cursor, colsrc);                 // 10

    float* hc = hA;
    float* hn = hB;
    for (int l = 0; l < 4; l++) {
        if (l > 0)
            k_pool5<<<mma_blocks, MTPB, mma_smem>>>(hc, Wp2 + l * HID * HID,
                                                    b_pool + l * HID, hp);
        k_agg3<<<(NN + 7) / 8, 256>>>(hp, rowptr, colsrc, agg);
        k_apply5<<<mma_blocks, MTPB, mma_smem>>>(hc, agg, Wa2 + l * 2 * HID * HID,
                                                 b_app + l * HID, hn);
        float* tmp = hc; hc = hn; hn = tmp;
    }

    // readout
    k_zero<<<(GG * HID + 255) / 256, 256>>>(gsum, GG * HID);
    k_zero<<<(GG + 255) / 256, 256>>>(gcnt, GG);
    k_gsum2<<<(NN + GNB - 1) / GNB, 128>>>(hc, gid, gsum, gcnt);
    k_mlp<<<GG, 128>>>(gsum, gcnt, W1, b1, W2, b2, W3, b3, out);
}